// round 17
// baseline (speedup 1.0000x reference)
#include <cuda_runtime.h>
#include <cstdint>

#define S_TOT 32768
#define CH    16
#define NCHUNK (S_TOT / CH)

// ---------------- static device scratch (16B aligned) ----------------
__device__ __align__(16) float g_fc1[65536u * 128u];
__device__ __align__(16) float g_xg0[2u * 32768u * 512u];   // PERMUTED: [t][e*4+g]
__device__ __align__(16) float g_xg1[2u * 32768u * 512u];   // PERMUTED
__device__ __align__(16) unsigned short g_h0bf[2u * 32768u * 128u];  // h0 stream as bf16
__device__ __align__(16) float g_y  [2u * 256u * 128u];
__device__ __align__(16) unsigned g_wpk[3u * 512u * 64u];   // bf16x2 pairs: WhhL0, WhhL1, WihL1
__device__ int g_prog[4];  // [seq]: L0 chunk flag; [2+seq]: producer flag

// ---------------- helpers ----------------
__device__ __forceinline__ int ld_acq(const int* p) {
    int v;
    asm volatile("ld.acquire.gpu.b32 %0, [%1];" : "=r"(v) : "l"(p) : "memory");
    return v;
}
__device__ __forceinline__ void st_rel(int* p, int v) {
    asm volatile("st.release.gpu.b32 [%0], %1;" :: "l"(p), "r"(v) : "memory");
}
__device__ __forceinline__ void barn(int id, int cnt) {
    asm volatile("bar.sync %0, %1;" :: "r"(id), "r"(cnt) : "memory");
}
__device__ __forceinline__ unsigned bf16rn_bits(float f) {
    unsigned u = __float_as_uint(f);
    return ((u + 0x7fffu + ((u >> 16) & 1u)) >> 16) & 0xffffu;
}
__device__ __forceinline__ float tanhap(float x) {
    float r;
    asm("tanh.approx.f32 %0, %1;" : "=f"(r) : "f"(x));
    return r;
}
__device__ __forceinline__ float sigap(float x) {
    return fmaf(0.5f, tanhap(0.5f * x), 0.5f);
}
__device__ __forceinline__ void hfma2(unsigned& acc, unsigned a, unsigned b) {
    asm("fma.rn.bf16x2 %0, %1, %2, %0;" : "+r"(acc) : "r"(a), "r"(b));
}
__device__ __forceinline__ unsigned hadd2v(unsigned a, unsigned b) {
    unsigned d;
    asm("fma.rn.bf16x2 %0, %1, %2, %3;" : "=r"(d) : "r"(a), "r"(0x3F803F80u), "r"(b));
    return d;
}
__device__ __forceinline__ float bf_lo(unsigned w) { return __uint_as_float(w << 16); }
__device__ __forceinline__ float bf_hi(unsigned w) { return __uint_as_float(w & 0xffff0000u); }

// ---------------- prep: bf16x2-pack WhhL0, WhhL1, WihL1; reset flags ----------------
__global__ void __launch_bounds__(512) prep_kernel(const float* __restrict__ Wih,
                                                   const float* __restrict__ Whh) {
    int wsel = blockIdx.x, j = threadIdx.x;
    const float* row;
    if (wsel == 0)      row = Whh + (size_t)j * 128;
    else if (wsel == 1) row = Whh + 512u * 128u + (size_t)j * 128;
    else                row = Wih + 512u * 128u + (size_t)j * 128;
    unsigned* dst = g_wpk + ((size_t)wsel * 512 + j) * 64;
    for (int p = 0; p < 64; p++)
        dst[p] = bf16rn_bits(row[2 * p]) | (bf16rn_bits(row[2 * p + 1]) << 16);
    if (wsel == 0 && j < 4) g_prog[j] = 0;
}

// ---------------- fc1 = relu(x @ Wfc^T + b) ----------------
__global__ void __launch_bounds__(256) fc1_kernel(const float* __restrict__ inp1,
                                                  const float* __restrict__ inp2,
                                                  const float* __restrict__ Wfc,
                                                  const float* __restrict__ bfc) {
    __shared__ __align__(16) float Ws[128][65];
    __shared__ __align__(16) float As[32][64];
    int tid = threadIdx.x;
    for (int i = tid; i < 128 * 64; i += 256) Ws[i >> 6][i & 63] = Wfc[i];
    int r0 = blockIdx.x * 32;
    for (int i = tid; i < 32 * 64; i += 256) {
        int r = r0 + (i >> 6), k = i & 63;
        const float* src = (r < S_TOT) ? (inp1 + (size_t)r * 64)
                                       : (inp2 + (size_t)(r - S_TOT) * 64);
        As[i >> 6][k] = src[k];
    }
    __syncthreads();
    int n = tid & 127, rb = (tid >> 7) * 16;
    float b = bfc[n];
    for (int rr = 0; rr < 16; rr++) {
        float acc = b;
#pragma unroll
        for (int k = 0; k < 64; k++) acc = fmaf(As[rb + rr][k], Ws[n][k], acc);
        g_fc1[(size_t)(r0 + rb + rr) * 128 + n] = fmaxf(acc, 0.f);
    }
}

// ---------------- xg0 = fc1 @ Wih0^T + (bih0+bhh0), PERMUTED store ----------------
__global__ void __launch_bounds__(256) xg0_kernel(const float* __restrict__ Wih,
                                                  const float* __restrict__ bih,
                                                  const float* __restrict__ bhh) {
    __shared__ __align__(16) float As[64][68];
    __shared__ __align__(16) float Bs[64][68];
    int m0 = blockIdx.x * 64, n0 = blockIdx.y * 64;
    int tid = threadIdx.x;
    int tx = tid & 15, ty = tid >> 4;
    float acc[4][4] = {};
    for (int kt = 0; kt < 128; kt += 64) {
        for (int i = tid; i < 64 * 16; i += 256) {
            int r = i >> 4, c = (i & 15) * 4;
            float4 v = *(const float4*)(g_fc1 + (size_t)(m0 + r) * 128 + kt + c);
            As[c + 0][r] = v.x; As[c + 1][r] = v.y; As[c + 2][r] = v.z; As[c + 3][r] = v.w;
        }
        for (int i = tid; i < 64 * 16; i += 256) {
            int r = i >> 4, c = (i & 15) * 4;
            float4 v = *(const float4*)(Wih + (size_t)(n0 + r) * 128 + kt + c);
            Bs[c + 0][r] = v.x; Bs[c + 1][r] = v.y; Bs[c + 2][r] = v.z; Bs[c + 3][r] = v.w;
        }
        __syncthreads();
#pragma unroll
        for (int k = 0; k < 64; k++) {
            float4 a4 = *(const float4*)&As[k][ty * 4];
            float4 b4 = *(const float4*)&Bs[k][tx * 4];
            float a[4] = {a4.x, a4.y, a4.z, a4.w};
            float bb[4] = {b4.x, b4.y, b4.z, b4.w};
#pragma unroll
            for (int x = 0; x < 4; x++)
#pragma unroll
                for (int y = 0; y < 4; y++) acc[x][y] = fmaf(a[x], bb[y], acc[x][y]);
        }
        __syncthreads();
    }
#pragma unroll
    for (int x = 0; x < 4; x++) {
        int m = m0 + ty * 4 + x;
#pragma unroll
        for (int y = 0; y < 4; y++) {
            int n = n0 + tx * 4 + y;
            int pn = (n & 127) * 4 + (n >> 7);   // permuted position
            g_xg0[(size_t)m * 512 + pn] = acc[x][y] + bih[n] + bhh[n];
        }
    }
}

// ---------------- paired recurrence: both sequences in one CTA ----------------
// 256 compute threads (e = tid>>1, p = tid&1; rows row0/row1 shared by both seqs)
// + 2 staging warps (warp 8 -> seq0 xg, warp 9 -> seq1 xg).
#define XGS_OFF 0
#define HBF_OFF 131072
#define DSM_REC (131072 + 1024)

__device__ void rec_pair(char* dsm, const unsigned* __restrict__ wpk_layer,
                         const float* __restrict__ xgA, const float* __restrict__ xgB,
                         unsigned short* __restrict__ hsA, unsigned short* __restrict__ hsB,
                         float* __restrict__ yA, float* __restrict__ yB,
                         const int* wfA, const int* wfB, int* sfA, int* sfB)
{
    float (*xgs)[2][CH][512] = (float (*)[2][CH][512])(dsm + XGS_OFF);  // [seq][buf][s][n]
    unsigned short (*hbf)[2][128] = (unsigned short (*)[2][128])(dsm + HBF_OFF); // [seq][par][e]
    int tid = threadIdx.x;

    if (tid >= 256) {
        // ---- staging warps: warp 8 -> seq0, warp 9 -> seq1 ----
        int ws = (tid - 256) >> 5, lt = tid & 31;
        const float* src_base = ws ? xgB : xgA;
        const int* wf = ws ? wfB : wfA;
        int* sf = ws ? sfB : sfA;
        if (wf && lt == 0) { while (ld_acq(wf) < 1) {} }
        __syncwarp();
        {
            const float4* src = (const float4*)src_base;
            float4* dst = (float4*)&xgs[ws][0][0][0];
            for (int i = lt; i < 2048; i += 32) dst[i] = src[i];
        }
        barn(0, 320);
        for (int ck = 0; ck < NCHUNK; ck++) {
            if (ck + 1 < NCHUNK) {
                if (wf && lt == 0) { while (ld_acq(wf) < ck + 2) {} }
                __syncwarp();
                const float4* src = (const float4*)(src_base + (size_t)(ck + 1) * CH * 512);
                float4* dst = (float4*)&xgs[ws][(ck + 1) & 1][0][0];
                for (int i = lt; i < 2048; i += 32) dst[i] = src[i];
            }
            barn(0, 320);
            if (sf && lt == 0) {
                asm volatile("fence.acq_rel.gpu;" ::: "memory");
                st_rel(sf, ck + 1);
            }
        }
        return;
    }

    // ---- compute warps ----
    int e = tid >> 1, p = tid & 1;
    int row0 = p * 256 + e;                // i (p0) / g (p1)
    int row1 = row0 + 128;                 // f (p0) / o (p1)

    unsigned w0[64], w1[64];               // shared by both sequences
    {
        const unsigned* s0 = wpk_layer + (size_t)row0 * 64;
        const unsigned* s1 = wpk_layer + (size_t)row1 * 64;
#pragma unroll
        for (int i = 0; i < 64; i++) { w0[i] = s0[i]; w1[i] = s1[i]; }
    }
    float sel0 = p ? 1.0f : 0.5f;
    float aa0  = p ? 1.0f : 0.5f;
    float bb0  = p ? 0.0f : 0.5f;

    ((unsigned short*)hbf)[tid] = 0;       // zero all 512 h slots (2 seq x 2 par x 128)
    ((unsigned short*)hbf)[tid + 256] = 0;
    float cA = 0.f, cB = 0.f;
    barn(0, 320);                          // chunk 0 staged

    for (int ck = 0; ck < NCHUNK; ck++) {
        int buf = ck & 1;
#pragma unroll 1
        for (int s = 0; s < CH; s++) {
            int t = ck * CH + s;
            int par = t & 1;
            float2 xpA = *(const float2*)&xgs[0][buf][s][e * 4 + 2 * p];
            float2 xpB = *(const float2*)&xgs[1][buf][s][e * 4 + 2 * p];

            // --- dot A (pipe work) ---
            const uint4* hA = (const uint4*)&hbf[0][par][0];
            unsigned a0 = 0u, a1 = 0u, a2 = 0u, a3 = 0u;
            unsigned b0 = 0u, b1 = 0u, b2 = 0u, b3 = 0u;
#pragma unroll
            for (int q = 0; q < 16; q++) {
                uint4 hp = hA[q];
                hfma2(a0, w0[4 * q],     hp.x);
                hfma2(a1, w0[4 * q + 1], hp.y);
                hfma2(a2, w0[4 * q + 2], hp.z);
                hfma2(a3, w0[4 * q + 3], hp.w);
                hfma2(b0, w1[4 * q],     hp.x);
                hfma2(b1, w1[4 * q + 1], hp.y);
                hfma2(b2, w1[4 * q + 2], hp.z);
                hfma2(b3, w1[4 * q + 3], hp.w);
            }
            // --- dot B (pipe work, independent) ---
            const uint4* hB = (const uint4*)&hbf[1][par][0];
            unsigned d0 = 0u, d1 = 0u, d2 = 0u, d3 = 0u;
            unsigned f0 = 0u, f1 = 0u, f2 = 0u, f3 = 0u;
#pragma unroll
            for (int q = 0; q < 16; q++) {
                uint4 hp = hB[q];
                hfma2(d0, w0[4 * q],     hp.x);
                hfma2(d1, w0[4 * q + 1], hp.y);
                hfma2(d2, w0[4 * q + 2], hp.z);
                hfma2(d3, w0[4 * q + 3], hp.w);
                hfma2(f0, w1[4 * q],     hp.x);
                hfma2(f1, w1[4 * q + 1], hp.y);
                hfma2(f2, w1[4 * q + 2], hp.z);
                hfma2(f3, w1[4 * q + 3], hp.w);
            }

            // --- tail A ---
            unsigned sA0 = hadd2v(a0, a2), sA1 = hadd2v(a1, a3);
            unsigned tA0 = hadd2v(b0, b2), tA1 = hadd2v(b1, b3);
            float v0A = ((bf_lo(sA0) + bf_hi(sA0)) + (bf_lo(sA1) + bf_hi(sA1))) + xpA.x;
            float v1A = ((bf_lo(tA0) + bf_hi(tA0)) + (bf_lo(tA1) + bf_hi(tA1))) + xpA.y;
            float act0A = fmaf(aa0, tanhap(sel0 * v0A), bb0);
            float act1A = sigap(v1A);
            // --- tail B (independent ILP) ---
            unsigned sB0 = hadd2v(d0, d2), sB1 = hadd2v(d1, d3);
            unsigned tB0 = hadd2v(f0, f2), tB1 = hadd2v(f1, f3);
            float v0B = ((bf_lo(sB0) + bf_hi(sB0)) + (bf_lo(sB1) + bf_hi(sB1))) + xpB.x;
            float v1B = ((bf_lo(tB0) + bf_hi(tB0)) + (bf_lo(tB1) + bf_hi(tB1))) + xpB.y;
            float act0B = fmaf(aa0, tanhap(sel0 * v0B), bb0);
            float act1B = sigap(v1B);

            float xgA_ = __shfl_xor_sync(0xffffffffu, act0A, 1);
            float xoA_ = __shfl_xor_sync(0xffffffffu, act1A, 1);
            float xgB_ = __shfl_xor_sync(0xffffffffu, act0B, 1);
            float xoB_ = __shfl_xor_sync(0xffffffffu, act1B, 1);
            if (p == 0) {
                cA = fmaf(act1A, cA, act0A * xgA_);
                cB = fmaf(act1B, cB, act0B * xgB_);
                float hA_ = xoA_ * tanhap(cA);
                float hB_ = xoB_ * tanhap(cB);
                unsigned short hbA, hbB;
                asm("cvt.rn.bf16.f32 %0, %1;" : "=h"(hbA) : "f"(hA_));
                asm("cvt.rn.bf16.f32 %0, %1;" : "=h"(hbB) : "f"(hB_));
                hbf[0][par ^ 1][e] = hbA;
                hbf[1][par ^ 1][e] = hbB;
                if (hsA) {
                    hsA[(size_t)t * 128 + e] = hbA;
                    hsB[(size_t)t * 128 + e] = hbB;
                }
                if (yA && t >= S_TOT - 256) {
                    yA[(size_t)(t - (S_TOT - 256)) * 128 + e] = hA_;
                    yB[(size_t)(t - (S_TOT - 256)) * 128 + e] = hB_;
                }
            }
            if (s != CH - 1) barn(1, 256);
        }
        barn(0, 320);
    }
}

// ---------------- xg1 producer: per-seq CTA, 256 threads, bf16 input ----------------
__device__ void producer(char* dsm, int seq,
                         const float* __restrict__ bih, const float* __restrict__ bhh)
{
    unsigned* h0bf = (unsigned*)dsm;       // CH*64 bf16x2 words (4KB)
    int tid = threadIdx.x;                 // 0..255, rows tid and tid+256
    unsigned wA[64], wB[64];
    {
        const unsigned* sA = g_wpk + 2u * 512u * 64u + (size_t)tid * 64;
        const unsigned* sB = sA + 256u * 64u;
#pragma unroll
        for (int i = 0; i < 64; i++) { wA[i] = sA[i]; wB[i] = sB[i]; }
    }
    float bA = bih[512 + tid] + bhh[512 + tid];
    float bB = bih[768 + tid] + bhh[768 + tid];
    int pnA = (tid & 127) * 4 + (tid >> 7);
    int pnB = pnA + 2;
    const unsigned* h0w = (const unsigned*)(g_h0bf + (size_t)seq * S_TOT * 128);
    float* xg1 = g_xg1 + (size_t)seq * S_TOT * 512;
    const int* wflag = &g_prog[seq];
    int* sflag = &g_prog[2 + seq];

    for (int ck = 0; ck < NCHUNK; ck++) {
        if (tid == 0) { while (ld_acq(wflag) < ck + 1) {} }
        barn(0, 256);
        ((uint4*)h0bf)[tid] = ((const uint4*)(h0w + (size_t)ck * CH * 64))[tid];
        barn(0, 256);
#pragma unroll 1
        for (int ss = 0; ss < CH; ss++) {
            const uint4* h4 = (const uint4*)&h0bf[ss * 64];
            unsigned a0 = 0u, a1 = 0u, a2 = 0u, a3 = 0u;
            unsigned c0 = 0u, c1 = 0u, c2 = 0u, c3 = 0u;
#pragma unroll
            for (int q = 0; q < 16; q++) {
                uint4 hp = h4[q];
                hfma2(a0, wA[4 * q],     hp.x);
                hfma2(a1, wA[4 * q + 1], hp.y);
                hfma2(a2, wA[4 * q + 2], hp.z);
                hfma2(a3, wA[4 * q + 3], hp.w);
                hfma2(c0, wB[4 * q],     hp.x);
                hfma2(c1, wB[4 * q + 1], hp.y);
                hfma2(c2, wB[4 * q + 2], hp.z);
                hfma2(c3, wB[4 * q + 3], hp.w);
            }
            unsigned s0w = hadd2v(a0, a2), s1w = hadd2v(a1, a3);
            unsigned t0w = hadd2v(c0, c2), t1w = hadd2v(c1, c3);
            float vA = ((bf_lo(s0w) + bf_hi(s0w)) + (bf_lo(s1w) + bf_hi(s1w))) + bA;
            float vB = ((bf_lo(t0w) + bf_hi(t0w)) + (bf_lo(t1w) + bf_hi(t1w))) + bB;
            float* dst = xg1 + (size_t)(ck * CH + ss) * 512;
            dst[pnA] = vA;
            dst[pnB] = vB;
        }
        barn(0, 256);
        if (tid == 0) {
            asm volatile("fence.acq_rel.gpu;" ::: "memory");
            st_rel(sflag, ck + 1);
        }
    }
}

// ---------------- pipeline: 4 CTAs = {L0 pair, L1 pair, producer s0, producer s1} ----------------
__global__ void __launch_bounds__(320, 1)
pipeline4(const float* __restrict__ bih, const float* __restrict__ bhh) {
    extern __shared__ char dsm[];
    int b = blockIdx.x;
    if (b == 0) {
        rec_pair(dsm, g_wpk,
                 g_xg0, g_xg0 + (size_t)S_TOT * 512,
                 g_h0bf, g_h0bf + (size_t)S_TOT * 128,
                 nullptr, nullptr,
                 nullptr, nullptr, &g_prog[0], &g_prog[1]);
    } else if (b == 1) {
        rec_pair(dsm, g_wpk + 512u * 64u,
                 g_xg1, g_xg1 + (size_t)S_TOT * 512,
                 nullptr, nullptr,
                 g_y, g_y + 256u * 128u,
                 &g_prog[2], &g_prog[3], nullptr, nullptr);
    } else {
        if (threadIdx.x >= 256) return;
        producer(dsm, b - 2, bih, bhh);
    }
}

// ---------------- head ----------------
__global__ void __launch_bounds__(256) head_kernel(const float* __restrict__ Wh,
                                                   const float* __restrict__ bh,
                                                   float* __restrict__ out) {
    int r = threadIdx.x;
    const float* y1 = g_y + (size_t)r * 128;
    const float* y2 = g_y + 256u * 128u + (size_t)r * 128;
    float s1 = 0.f, s2 = 0.f;
#pragma unroll 8
    for (int k = 0; k < 128; k++) {
        float d = y1[k] - y2[k];
        float w = Wh[k];
        s1 = fmaf(w, fmaxf(d, 0.f), s1);
        s2 = fmaf(w, fmaxf(-d, 0.f), s2);
    }
    float b = bh[0];
    float p1 = s1 + b, p2 = s2 + b, pd = (s1 - s2) + b;
    float m = fmaxf(p1, fmaxf(p2, pd));
    float e1 = expf(p1 - m), e2 = expf(p2 - m), e3 = expf(pd - m);
    float inv = 1.f / (e1 + e2 + e3);
    out[r * 3 + 0] = e1 * inv;
    out[r * 3 + 1] = e2 * inv;
    out[r * 3 + 2] = e3 * inv;
}

// ---------------- launch ----------------
extern "C" void kernel_launch(void* const* d_in, const int* in_sizes, int n_in,
                              void* d_out, int out_size) {
    const float* inp1  = (const float*)d_in[0];
    const float* inp2  = (const float*)d_in[1];
    const float* Wfc   = (const float*)d_in[2];
    const float* bfc   = (const float*)d_in[3];
    const float* Wih   = (const float*)d_in[4];
    const float* Whh   = (const float*)d_in[5];
    const float* bih   = (const float*)d_in[6];
    const float* bhh   = (const float*)d_in[7];
    const float* Whead = (const float*)d_in[8];
    const float* bhead = (const float*)d_in[9];
    float* out = (float*)d_out;

    cudaFuncSetAttribute(pipeline4, cudaFuncAttributeMaxDynamicSharedMemorySize, DSM_REC);

    prep_kernel<<<3, 512>>>(Wih, Whh);
    fc1_kernel<<<2048, 256>>>(inp1, inp2, Wfc, bfc);
    xg0_kernel<<<dim3(1024, 8), 256>>>(Wih, bih, bhh);
    pipeline4<<<4, 320, DSM_REC>>>(bih, bhh);
    head_kernel<<<1, 256>>>(Whead, bhead, out);
}